// round 9
// baseline (speedup 1.0000x reference)
#include <cuda_runtime.h>

#define N_B    64
#define T_LEN  2048
#define IN_D   8
#define C_CH   2
#define STEPS  2047
#define LCHUNK 32
#define NCHUNK 64
#define WPB    4
#define NCHAIN (N_B * C_CH)          // 128
#define NWARPS (NCHAIN * NCHUNK)     // 8192
#define FULLM  0xffffffffu

__device__ __align__(16) float g_part [NWARPS * 100];
__device__ __align__(16) float g_part2[NCHAIN * 8 * 100];

// ---- LDS-side helpers (dense stride-10, float2) ----
__device__ __forceinline__ void ldrow(const float* __restrict__ m, int r,
                                      float o[10]) {
#pragma unroll
    for (int i = 0; i < 10; i += 2) {
        float2 v = *(const float2*)(m + r * 10 + i);
        o[i] = v.x; o[i + 1] = v.y;
    }
}
__device__ __forceinline__ void ldrow2(const float* __restrict__ m, int r,
                                       float o0[10], float o1[10]) {
    ldrow(m, r, o0); ldrow(m, r + 1, o1);
}
__device__ __forceinline__ void ip22(const float A0[10], const float A1[10],
                                     const float B0[10], const float B1[10],
                                     float& o00, float& o01, float& o10, float& o11) {
#pragma unroll
    for (int i = 0; i < 10; ++i) {
        o00 = fmaf(A0[i], B0[i], o00); o01 = fmaf(A0[i], B1[i], o01);
        o10 = fmaf(A1[i], B0[i], o10); o11 = fmaf(A1[i], B1[i], o11);
    }
}
__device__ __forceinline__ void ip22n(const float A0[10], const float A1[10],
                                      const float B0[10], const float B1[10],
                                      float& o00, float& o01, float& o10, float& o11) {
#pragma unroll
    for (int i = 0; i < 10; ++i) {
        o00 = fmaf(A0[i], -B0[i], o00); o01 = fmaf(A0[i], -B1[i], o01);
        o10 = fmaf(A1[i], -B0[i], o10); o11 = fmaf(A1[i], -B1[i], o11);
    }
}
__device__ __forceinline__ void st22(float* __restrict__ B, int r0, int c0,
                                     float v00, float v01, float v10, float v11) {
    *(float2*)(B + r0 * 10 + c0)       = make_float2(v00, v01);
    *(float2*)(B + (r0 + 1) * 10 + c0) = make_float2(v10, v11);
}

// ---------------------------------------------------------------------------
// Kernel 1: one warp per (chain, chunk). Order-7 Taylor expm of skew G.
// W, P via shared-memory row strips (Gr, Wr cached); V6, E, Acc via
// register-distributed tiles exchanged with __shfl_sync (no smem, no syncs).
// Lane l<25 owns tile (j2=l/5, k2=l%5); lanes 25-31 duplicate lane 24.
// ---------------------------------------------------------------------------
__global__ void __launch_bounds__(128) step_kernel(const float* __restrict__ x,
                                                   const float* __restrict__ A) {
    __shared__ float sk[C_CH * IN_D * 100];
    __shared__ float xs[WPB][(LCHUNK + 1) * IN_D];
    __shared__ __align__(16) float dxs[WPB][LCHUNK * IN_D];
    __shared__ __align__(16) float mats[WPB][2][100];   // bG, bW only

    int tid = threadIdx.x;

    // skew = A - A^T
    for (int idx = tid; idx < C_CH * IN_D * 100; idx += 128) {
        int jk = idx % 100, ci = idx / 100;
        int j = jk / 10, k = jk % 10;
        sk[idx] = A[ci * 100 + j * 10 + k] - A[ci * 100 + k * 10 + j];
    }

    int warp = tid >> 5, lane = tid & 31;
    int w     = blockIdx.x * WPB + warp;
    int chunk = w & (NCHUNK - 1);
    int chain = w >> 6;
    int c     = chain & 1;
    int n     = chain >> 1;
    int t0    = chunk * LCHUNK;
    int nsteps = min(LCHUNK, STEPS - t0);

    const float* xp = x + ((size_t)n * T_LEN + t0) * IN_D;
    float* xw = xs[warp];
    int cnt = (nsteps + 1) * IN_D;
    for (int idx = lane; idx < cnt; idx += 32) xw[idx] = xp[idx];
    __syncthreads();

    float* dxp = dxs[warp];
    for (int idx = lane; idx < nsteps * IN_D; idx += 32)
        dxp[idx] = xw[idx + IN_D] - xw[idx];

    bool act = lane < 25;
    int l  = act ? lane : 24;
    int j2 = l / 5, k2 = l % 5;
    int r0 = 2 * j2, c0 = 2 * k2;
    float dI = (j2 == k2) ? 1.f : 0.f;

    // skew tiles -> registers
    const float* skc = sk + c * IN_D * 100;
    float ska[IN_D][4];
#pragma unroll
    for (int i = 0; i < IN_D; ++i) {
        float2 a0 = *(const float2*)(skc + i * 100 + r0 * 10 + c0);
        float2 a1 = *(const float2*)(skc + i * 100 + r0 * 10 + 10 + c0);
        ska[i][0] = a0.x; ska[i][1] = a0.y; ska[i][2] = a1.x; ska[i][3] = a1.y;
    }

    float* bG = mats[warp][0];
    float* bW = mats[warp][1];

    const float c2 = 0.5f,      c4 = 1.f / 24.f,  c6 = 1.f / 720.f;
    const float s2 = 1.f / 6.f, s4 = 1.f / 120.f, s6 = 1.f / 5040.f;

    // Acc tile in registers (distributed across lanes)
    float ac00 = dI, ac01 = 0.f, ac10 = 0.f, ac11 = dI;

    float Gr0[10], Gr1[10], Wr0[10], Wr1[10], T0[10], T1[10];

    for (int t = 0; t < nsteps; ++t) {
        // ---- G tile (registers) ----
        const float* d = dxp + t * IN_D;
        float4 dA4 = *(const float4*)(d);
        float4 dB4 = *(const float4*)(d + 4);
        float dv[8] = {dA4.x, dA4.y, dA4.z, dA4.w, dB4.x, dB4.y, dB4.z, dB4.w};
        float g00 = 0.f, g01 = 0.f, g10 = 0.f, g11 = 0.f;
#pragma unroll
        for (int i = 0; i < 8; ++i) {
            g00 = fmaf(dv[i], ska[i][0], g00); g01 = fmaf(dv[i], ska[i][1], g01);
            g10 = fmaf(dv[i], ska[i][2], g10); g11 = fmaf(dv[i], ska[i][3], g11);
        }
        if (act) st22(bG, r0, c0, g00, g01, g10, g11);
        __syncwarp();

        // ---- W = G@G = -(Grows_r . Grows_c) via LDS ----
        ldrow2(bG, r0, Gr0, Gr1);                  // cached for E
        ldrow2(bG, c0, T0, T1);
        float w00 = 0.f, w01 = 0.f, w10 = 0.f, w11 = 0.f;
        ip22n(Gr0, Gr1, T0, T1, w00, w01, w10, w11);
        if (act) st22(bW, r0, c0, w00, w01, w10, w11);
        __syncwarp();

        // ---- P = W@W via LDS (no store; tile stays in regs) ----
        ldrow2(bW, r0, Wr0, Wr1);                  // cached for V6
        ldrow2(bW, c0, T0, T1);
        float p00 = 0.f, p01 = 0.f, p10 = 0.f, p11 = 0.f;
        ip22(Wr0, Wr1, T0, T1, p00, p01, p10, p11);

        // low-order C,S folds
        float C00 = fmaf(c4, p00, fmaf(c2, w00, dI));
        float C01 = fmaf(c4, p01, c2 * w01);
        float C10 = fmaf(c4, p10, c2 * w10);
        float C11 = fmaf(c4, p11, fmaf(c2, w11, dI));
        float S00 = fmaf(s4, p00, fmaf(s2, w00, dI));
        float S01 = fmaf(s4, p01, s2 * w01);
        float S10 = fmaf(s4, p10, s2 * w10);
        float S11 = fmaf(s4, p11, fmaf(s2, w11, dI));

        // ---- V6 = W@P via SHFL (B tiles P(i,k2) from lane i*5+k2) ----
        float v00 = 0.f, v01 = 0.f, v10 = 0.f, v11 = 0.f;
#pragma unroll
        for (int i = 0; i < 5; ++i) {
            int src = i * 5 + k2;
            float b00 = __shfl_sync(FULLM, p00, src);
            float b01 = __shfl_sync(FULLM, p01, src);
            float b10 = __shfl_sync(FULLM, p10, src);
            float b11 = __shfl_sync(FULLM, p11, src);
            float a00 = Wr0[2*i], a01 = Wr0[2*i+1], a10 = Wr1[2*i], a11 = Wr1[2*i+1];
            v00 = fmaf(a00, b00, v00); v00 = fmaf(a01, b10, v00);
            v01 = fmaf(a00, b01, v01); v01 = fmaf(a01, b11, v01);
            v10 = fmaf(a10, b00, v10); v10 = fmaf(a11, b10, v10);
            v11 = fmaf(a10, b01, v11); v11 = fmaf(a11, b11, v11);
        }
        C00 = fmaf(c6, v00, C00); C01 = fmaf(c6, v01, C01);
        C10 = fmaf(c6, v10, C10); C11 = fmaf(c6, v11, C11);
        S00 = fmaf(s6, v00, S00); S01 = fmaf(s6, v01, S01);
        S10 = fmaf(s6, v10, S10); S11 = fmaf(s6, v11, S11);

        // ---- E = C + G@S via SHFL (S tiles from lane i*5+k2; Gr cached) ----
        float e00 = C00, e01 = C01, e10 = C10, e11 = C11;
#pragma unroll
        for (int i = 0; i < 5; ++i) {
            int src = i * 5 + k2;
            float b00 = __shfl_sync(FULLM, S00, src);
            float b01 = __shfl_sync(FULLM, S01, src);
            float b10 = __shfl_sync(FULLM, S10, src);
            float b11 = __shfl_sync(FULLM, S11, src);
            float a00 = Gr0[2*i], a01 = Gr0[2*i+1], a10 = Gr1[2*i], a11 = Gr1[2*i+1];
            e00 = fmaf(a00, b00, e00); e00 = fmaf(a01, b10, e00);
            e01 = fmaf(a00, b01, e01); e01 = fmaf(a01, b11, e01);
            e10 = fmaf(a10, b00, e10); e10 = fmaf(a11, b10, e10);
            e11 = fmaf(a10, b01, e11); e11 = fmaf(a11, b11, e11);
        }

        // ---- Acc = Acc @ E via SHFL (both operands register-distributed) ----
        float na00 = 0.f, na01 = 0.f, na10 = 0.f, na11 = 0.f;
#pragma unroll
        for (int i = 0; i < 5; ++i) {
            int sa = j2 * 5 + i;
            int sb = i * 5 + k2;
            float a00 = __shfl_sync(FULLM, ac00, sa);
            float a01 = __shfl_sync(FULLM, ac01, sa);
            float a10 = __shfl_sync(FULLM, ac10, sa);
            float a11 = __shfl_sync(FULLM, ac11, sa);
            float b00 = __shfl_sync(FULLM, e00, sb);
            float b01 = __shfl_sync(FULLM, e01, sb);
            float b10 = __shfl_sync(FULLM, e10, sb);
            float b11 = __shfl_sync(FULLM, e11, sb);
            na00 = fmaf(a00, b00, na00); na00 = fmaf(a01, b10, na00);
            na01 = fmaf(a00, b01, na01); na01 = fmaf(a01, b11, na01);
            na10 = fmaf(a10, b00, na10); na10 = fmaf(a11, b10, na10);
            na11 = fmaf(a10, b01, na11); na11 = fmaf(a11, b11, na11);
        }
        ac00 = na00; ac01 = na01; ac10 = na10; ac11 = na11;
    }

    // write chunk partial from register tiles
    if (act) {
        float* pp = g_part + (size_t)w * 100;
        *(float2*)(pp + r0 * 10 + c0)       = make_float2(ac00, ac01);
        *(float2*)(pp + (r0 + 1) * 10 + c0) = make_float2(ac10, ac11);
    }
}

// ---------------------------------------------------------------------------
// Tree combine (unchanged)
// ---------------------------------------------------------------------------
__device__ __forceinline__ void cmm22(const float* __restrict__ Am,
                                      const float* __restrict__ Bm,
                                      int r0, int c0,
                                      float& o00, float& o01, float& o10, float& o11) {
    o00 = 0.f; o01 = 0.f; o10 = 0.f; o11 = 0.f;
#pragma unroll
    for (int i = 0; i < 10; i += 2) {
        float2 a0 = *(const float2*)(Am + r0 * 10 + i);
        float2 a1 = *(const float2*)(Am + r0 * 10 + 10 + i);
        float2 b0 = *(const float2*)(Bm + i * 10 + c0);
        float2 b1 = *(const float2*)(Bm + (i + 1) * 10 + c0);
        o00 = fmaf(a0.x, b0.x, o00); o00 = fmaf(a0.y, b1.x, o00);
        o01 = fmaf(a0.x, b0.y, o01); o01 = fmaf(a0.y, b1.y, o01);
        o10 = fmaf(a1.x, b0.x, o10); o10 = fmaf(a1.y, b1.x, o10);
        o11 = fmaf(a1.x, b0.y, o11); o11 = fmaf(a1.y, b1.y, o11);
    }
}

__device__ __forceinline__ void combine_run(const float* __restrict__ src,
                                            float* __restrict__ dst,
                                            float* Ac0, float* Ac1, float* Pb,
                                            int lane, int cntp) {
    bool act = lane < 25;
    int l  = act ? lane : 24;
    int j2 = l / 5, k2 = l % 5;
    int r0 = 2 * j2, c0 = 2 * k2;

    if (act) *(float4*)(Ac0 + lane * 4) = *(const float4*)(src + lane * 4);
    __syncwarp();

    float* cur = Ac0;
    float* nxt = Ac1;
    for (int p = 1; p < cntp; ++p) {
        if (act) *(float4*)(Pb + lane * 4) = *(const float4*)(src + p * 100 + lane * 4);
        __syncwarp();
        float o00, o01, o10, o11;
        cmm22(cur, Pb, r0, c0, o00, o01, o10, o11);
        if (act) st22(nxt, r0, c0, o00, o01, o10, o11);
        __syncwarp();
        float* tmp = cur; cur = nxt; nxt = tmp;
    }
    if (act) *(float4*)(dst + lane * 4) = *(const float4*)(cur + lane * 4);
}

__global__ void __launch_bounds__(128) combineA() {
    __shared__ __align__(16) float sm[WPB][3][100];
    int warp = threadIdx.x >> 5, lane = threadIdx.x & 31;
    int w = blockIdx.x * WPB + warp;          // [0, 1024)
    int chain = w >> 3, g = w & 7;
    combine_run(g_part + ((size_t)chain * NCHUNK + g * 8) * 100,
                g_part2 + ((size_t)chain * 8 + g) * 100,
                sm[warp][0], sm[warp][1], sm[warp][2], lane, 8);
}

__global__ void __launch_bounds__(128) combineB(float* __restrict__ out) {
    __shared__ __align__(16) float sm[WPB][3][100];
    int warp = threadIdx.x >> 5, lane = threadIdx.x & 31;
    int chain = blockIdx.x * WPB + warp;      // [0, 128)
    combine_run(g_part2 + (size_t)chain * 8 * 100,
                out + (size_t)chain * 100,
                sm[warp][0], sm[warp][1], sm[warp][2], lane, 8);
}

extern "C" void kernel_launch(void* const* d_in, const int* in_sizes, int n_in,
                              void* d_out, int out_size) {
    const float* x = (const float*)d_in[0];
    const float* A = (const float*)d_in[1];
    if (n_in >= 2 && in_sizes[0] < in_sizes[1]) {
        const float* t = x; x = A; A = t;
    }

    step_kernel<<<NWARPS / WPB, 128>>>(x, A);
    combineA<<<1024 / WPB, 128>>>();
    combineB<<<128 / WPB, 128>>>((float*)d_out);
}